// round 2
// baseline (speedup 1.0000x reference)
#include <cuda_runtime.h>
#include <cuda_bf16.h>

// ht[b,d] = sum_{s=start}^{start+x-1} hidden[b,s,d]
// start = sum(mask[B-1, :]) - x   (only the LAST batch row of mask matters)
//
// NOTE: the reference is JAX with x64 disabled -> mask dtype=jnp.int64 is
// silently downcast to int32, and the scalar x is int32. Read both as int32.
//
// Grid: B * (D/128) blocks. Block: 256 threads = 32 float4-cols x 8 s-groups.
// Each block independently reduces the last mask row (8KB int32, L2-cached
// after the first wave) so everything fits in ONE launch.

__global__ void __launch_bounds__(256)
srsmlp_window_sum_kernel(const float* __restrict__ hidden,
                         const int* __restrict__ mask,
                         const int* __restrict__ xptr,
                         float* __restrict__ out,
                         int B, int S, int D, int chunks /* D/128 */)
{
    const int tid  = threadIdx.x;
    const int col  = tid & 31;        // float4 column within 32-wide chunk
    const int sg   = tid >> 5;        // s-group 0..7
    const int b     = blockIdx.x / chunks;
    const int chunk = blockIdx.x - b * chunks;

    // ---- 1) block-local reduction of mask[B-1, :] -> session length ----
    __shared__ int s_len;
    if (tid == 0) s_len = 0;
    __syncthreads();

    {
        const int* mrow = mask + (long long)(B - 1) * S;
        int acc = 0;
        // vectorized int4 path for the aligned bulk (S % 4 == 0 in practice)
        const int S4 = S >> 2;
        const int4* mrow4 = reinterpret_cast<const int4*>(mrow);
        for (int i = tid; i < S4; i += 256) {
            int4 v = mrow4[i];
            acc += v.x + v.y + v.z + v.w;
        }
        for (int i = (S4 << 2) + tid; i < S; i += 256)  // tail (if S%4)
            acc += mrow[i];
        // warp reduce
        #pragma unroll
        for (int off = 16; off > 0; off >>= 1)
            acc += __shfl_down_sync(0xFFFFFFFFu, acc, off);
        if (col == 0)
            atomicAdd(&s_len, acc);
    }
    __syncthreads();

    const int x     = *xptr;
    const int start = s_len - x;

    // ---- 2) windowed sum over x rows, float4 per thread-column ----
    const int D4 = D >> 2;                      // float4 columns
    const int d4 = (chunk << 5) + col;          // this thread's float4 column
    const float4* __restrict__ base =
        reinterpret_cast<const float4*>(hidden) +
        ((long long)b * S + start) * D4 + d4;

    float4 sum = make_float4(0.f, 0.f, 0.f, 0.f);
    for (int r = sg; r < x; r += 8) {
        float4 v = base[(long long)r * D4];
        sum.x += v.x; sum.y += v.y; sum.z += v.z; sum.w += v.w;
    }

    // ---- 3) reduce the 8 s-groups in shared memory ----
    __shared__ float4 red[8][32];               // 4 KB
    red[sg][col] = sum;
    __syncthreads();

    if (sg == 0) {
        float4 t = red[0][col];
        #pragma unroll
        for (int j = 1; j < 8; ++j) {
            float4 v = red[j][col];
            t.x += v.x; t.y += v.y; t.z += v.z; t.w += v.w;
        }
        reinterpret_cast<float4*>(out)[(long long)b * D4 + d4] = t;
    }
}

extern "C" void kernel_launch(void* const* d_in, const int* in_sizes, int n_in,
                              void* d_out, int out_size)
{
    const float* hidden = (const float*)d_in[0];
    const int*   mask   = (const int*)d_in[1];
    const int*   xptr   = (const int*)d_in[2];
    float*       out    = (float*)d_out;

    const long long hidden_elems = in_sizes[0];
    const long long mask_elems   = in_sizes[1];

    const int D = (int)(hidden_elems / mask_elems);   // 1024
    const int B = out_size / D;                       // 32
    const int S = (int)(mask_elems / B);              // 2048
    const int chunks = D / 128;                       // 8 (D assumed %128==0)

    dim3 grid(B * chunks);
    srsmlp_window_sum_kernel<<<grid, 256>>>(hidden, mask, xptr, out,
                                            B, S, D, chunks);
}